// round 4
// baseline (speedup 1.0000x reference)
#include <cuda_runtime.h>
#include <cuda_bf16.h>

// COO SpMM, rows sorted: out[r] = sum_{(r,c,v)} v * x[c].  N=100000, E=1.6M, D=48.
// R4: warp-per-row (no intra-warp degree divergence). Lanes 0-11 process even
// edges, lanes 12-23 odd edges; each lane gathers one float4 of the 48-float x
// row via LDG.128. 4 edges per iteration for MLP. Single shuffle-fold epilogue.
// row_ptr built edge-parallel (streaming) instead of per-row binary search.

#define D_FEAT    48
#define D_VEC     12
#define MAX_NODES 100000

__device__ int g_row_ptr[MAX_NODES + 1];

// Edge-parallel CSR row-pointer build: thread e fills row starts in
// (rows[e-1], rows[e]]. Handles empty rows and both boundaries.
__global__ void build_row_ptr_edges(const int* __restrict__ rows, int E, int N) {
    int e = blockIdx.x * blockDim.x + threadIdx.x;
    if (e >= E) return;
    int r     = __ldg(&rows[e]);
    int rprev = (e == 0) ? -1 : __ldg(&rows[e - 1]);
    for (int rr = rprev + 1; rr <= r; rr++) g_row_ptr[rr] = e;
    if (e == E - 1) {
        for (int rr = r + 1; rr <= N; rr++) g_row_ptr[rr] = E;
    }
}

__global__ void __launch_bounds__(256)
spmm_warp_row_kernel(const float4* __restrict__ x4,
                     const int*    __restrict__ cols,
                     const float*  __restrict__ vals,
                     float4*       __restrict__ out4,
                     int N) {
    const int row = (blockIdx.x * blockDim.x + threadIdx.x) >> 5;
    if (row >= N) return;
    const int lane   = threadIdx.x & 31;
    const int g      = lane / 12;       // 0,1 active edge-groups; 2 = idle lanes
    const int fl     = lane % 12;       // float4 slot within the row
    const bool active = (lane < 24);

    int e = g_row_ptr[row];
    const int end = g_row_ptr[row + 1];

    float4 acc = make_float4(0.f, 0.f, 0.f, 0.f);

    // Main: 4 edges per iteration. Group g handles edges e+g and e+g+2.
    for (; e + 3 < end; e += 4) {
        if (active) {
            const int   c0 = __ldg(&cols[e + g]);
            const int   c1 = __ldg(&cols[e + g + 2]);
            const float v0 = __ldg(&vals[e + g]);
            const float v1 = __ldg(&vals[e + g + 2]);
            const float4 b0 = __ldg(&x4[(size_t)c0 * D_VEC + fl]);
            const float4 b1 = __ldg(&x4[(size_t)c1 * D_VEC + fl]);
            acc.x = fmaf(v0, b0.x, acc.x);
            acc.y = fmaf(v0, b0.y, acc.y);
            acc.z = fmaf(v0, b0.z, acc.z);
            acc.w = fmaf(v0, b0.w, acc.w);
            acc.x = fmaf(v1, b1.x, acc.x);
            acc.y = fmaf(v1, b1.y, acc.y);
            acc.z = fmaf(v1, b1.z, acc.z);
            acc.w = fmaf(v1, b1.w, acc.w);
        }
    }
    // Tail: 2 edges.
    if (e + 1 < end) {
        if (active) {
            const int   c = __ldg(&cols[e + g]);
            const float v = __ldg(&vals[e + g]);
            const float4 b = __ldg(&x4[(size_t)c * D_VEC + fl]);
            acc.x = fmaf(v, b.x, acc.x);
            acc.y = fmaf(v, b.y, acc.y);
            acc.z = fmaf(v, b.z, acc.z);
            acc.w = fmaf(v, b.w, acc.w);
        }
        e += 2;
    }
    // Tail: 1 edge (group 0 only).
    if (e < end) {
        if (lane < 12) {
            const int   c = __ldg(&cols[e]);
            const float v = __ldg(&vals[e]);
            const float4 b = __ldg(&x4[(size_t)c * D_VEC + fl]);
            acc.x = fmaf(v, b.x, acc.x);
            acc.y = fmaf(v, b.y, acc.y);
            acc.z = fmaf(v, b.z, acc.z);
            acc.w = fmaf(v, b.w, acc.w);
        }
    }

    // Fold group-1 partials (lanes 12-23) into group 0 (lanes 0-11).
    const unsigned FULL = 0xffffffffu;
    acc.x += __shfl_down_sync(FULL, acc.x, 12);
    acc.y += __shfl_down_sync(FULL, acc.y, 12);
    acc.z += __shfl_down_sync(FULL, acc.z, 12);
    acc.w += __shfl_down_sync(FULL, acc.w, 12);

    if (lane < 12) {
        out4[(size_t)row * D_VEC + fl] = acc;
    }
}

extern "C" void kernel_launch(void* const* d_in, const int* in_sizes, int n_in,
                              void* d_out, int out_size) {
    // metadata order: t, x, rows, cols, vals
    const float* x    = (const float*)d_in[1];
    const int*   rows = (const int*)d_in[2];
    const int*   cols = (const int*)d_in[3];
    const float* vals = (const float*)d_in[4];
    float*       out  = (float*)d_out;

    const int E = in_sizes[2];
    const int N = out_size / D_FEAT;

    {
        int threads = 256;
        int blocks  = (E + threads - 1) / threads;
        build_row_ptr_edges<<<blocks, threads>>>(rows, E, N);
    }
    {
        int threads = 256;                       // 8 warps = 8 rows per block
        int blocks  = (N * 32 + threads - 1) / threads;
        spmm_warp_row_kernel<<<blocks, threads>>>((const float4*)x, cols, vals,
                                                  (float4*)out, N);
    }
}

// round 7
// speedup vs baseline: 1.1151x; 1.1151x over previous
#include <cuda_runtime.h>
#include <cuda_bf16.h>

// COO SpMM, rows sorted: out[r] = sum_{(r,c,v)} v * x[c].  N=100000, E=1.6M, D=48.
// R5 = R3 (best kernel: row-parallel CSR, blockDim (12,16), one LDG.128 per
// edge per 12-lane group) + unroll-by-4 for memory-level parallelism (the
// measured bottleneck: latency-bound, issue=38%) + edge-parallel row_ptr build
// (measured ~free vs 3.7us binary search).
// (2nd resubmission — rounds 5 and 6 both hit GPU-broker acquisition
// timeouts; kernel has not yet run.)

#define D_FEAT    48
#define D_VEC     12
#define TPR       12
#define RPB       16
#define MAX_NODES 100000

__device__ int g_row_ptr[MAX_NODES + 1];

// Edge-parallel CSR row-pointer build: thread e fills row starts in
// (rows[e-1], rows[e]]. Handles empty rows and both boundaries.
__global__ void build_row_ptr_edges(const int* __restrict__ rows, int E, int N) {
    int e = blockIdx.x * blockDim.x + threadIdx.x;
    if (e >= E) return;
    int r     = __ldg(&rows[e]);
    int rprev = (e == 0) ? -1 : __ldg(&rows[e - 1]);
    for (int rr = rprev + 1; rr <= r; rr++) g_row_ptr[rr] = e;
    if (e == E - 1) {
        for (int rr = r + 1; rr <= N; rr++) g_row_ptr[rr] = E;
    }
}

__global__ void __launch_bounds__(TPR * RPB)
spmm_csr_vec4_kernel(const float4* __restrict__ x4,
                     const int*    __restrict__ cols,
                     const float*  __restrict__ vals,
                     float4*       __restrict__ out4,
                     int N) {
    const int row = blockIdx.x * RPB + threadIdx.y;
    if (row >= N) return;
    const int fl = threadIdx.x;              // 0..11: float4 slot in the row

    int e = g_row_ptr[row];
    const int end = g_row_ptr[row + 1];

    float4 acc = make_float4(0.f, 0.f, 0.f, 0.f);

    // Main loop: 4 edges per iteration -> 4 independent gathers in flight.
    for (; e + 3 < end; e += 4) {
        const int   c0 = __ldg(&cols[e]);
        const int   c1 = __ldg(&cols[e + 1]);
        const int   c2 = __ldg(&cols[e + 2]);
        const int   c3 = __ldg(&cols[e + 3]);
        const float v0 = __ldg(&vals[e]);
        const float v1 = __ldg(&vals[e + 1]);
        const float v2 = __ldg(&vals[e + 2]);
        const float v3 = __ldg(&vals[e + 3]);
        const float4 b0 = __ldg(&x4[(size_t)c0 * D_VEC + fl]);
        const float4 b1 = __ldg(&x4[(size_t)c1 * D_VEC + fl]);
        const float4 b2 = __ldg(&x4[(size_t)c2 * D_VEC + fl]);
        const float4 b3 = __ldg(&x4[(size_t)c3 * D_VEC + fl]);
        acc.x = fmaf(v0, b0.x, acc.x);
        acc.y = fmaf(v0, b0.y, acc.y);
        acc.z = fmaf(v0, b0.z, acc.z);
        acc.w = fmaf(v0, b0.w, acc.w);
        acc.x = fmaf(v1, b1.x, acc.x);
        acc.y = fmaf(v1, b1.y, acc.y);
        acc.z = fmaf(v1, b1.z, acc.z);
        acc.w = fmaf(v1, b1.w, acc.w);
        acc.x = fmaf(v2, b2.x, acc.x);
        acc.y = fmaf(v2, b2.y, acc.y);
        acc.z = fmaf(v2, b2.z, acc.z);
        acc.w = fmaf(v2, b2.w, acc.w);
        acc.x = fmaf(v3, b3.x, acc.x);
        acc.y = fmaf(v3, b3.y, acc.y);
        acc.z = fmaf(v3, b3.z, acc.z);
        acc.w = fmaf(v3, b3.w, acc.w);
    }
    // Tail: up to 3 edges.
    for (; e < end; e++) {
        const int   c = __ldg(&cols[e]);
        const float v = __ldg(&vals[e]);
        const float4 b = __ldg(&x4[(size_t)c * D_VEC + fl]);
        acc.x = fmaf(v, b.x, acc.x);
        acc.y = fmaf(v, b.y, acc.y);
        acc.z = fmaf(v, b.z, acc.z);
        acc.w = fmaf(v, b.w, acc.w);
    }

    out4[(size_t)row * D_VEC + fl] = acc;
}

extern "C" void kernel_launch(void* const* d_in, const int* in_sizes, int n_in,
                              void* d_out, int out_size) {
    // metadata order: t, x, rows, cols, vals
    const float* x    = (const float*)d_in[1];
    const int*   rows = (const int*)d_in[2];
    const int*   cols = (const int*)d_in[3];
    const float* vals = (const float*)d_in[4];
    float*       out  = (float*)d_out;

    const int E = in_sizes[2];
    const int N = out_size / D_FEAT;

    {
        int threads = 256;
        int blocks  = (E + threads - 1) / threads;
        build_row_ptr_edges<<<blocks, threads>>>(rows, E, N);
    }
    {
        dim3 block(TPR, RPB);
        int  grid = (N + RPB - 1) / RPB;
        spmm_csr_vec4_kernel<<<grid, block>>>((const float4*)x, cols, vals,
                                              (float4*)out, N);
    }
}

// round 8
// speedup vs baseline: 1.1293x; 1.0128x over previous
#include <cuda_runtime.h>
#include <cuda_bf16.h>

// COO SpMM, rows sorted: out[r] = sum_{(r,c,v)} v * x[c].  N=100000, E=1.6M, D=48.
// R8 = exact R3 spmm (best measured: 31.8us; row-parallel CSR, blockDim
// (12,16), unroll-2, one LDG.128 per edge per 12-lane row-group) composed with
// the edge-parallel row_ptr build (measured ~free in R5/R7 vs 3.7us for the
// binary-search build). Pure composition of two independently-measured parts.

#define D_FEAT    48
#define D_VEC     12
#define TPR       12
#define RPB       16
#define MAX_NODES 100000

__device__ int g_row_ptr[MAX_NODES + 1];

// Edge-parallel CSR row-pointer build: thread e fills row starts in
// (rows[e-1], rows[e]]. Handles empty rows and both boundaries.
__global__ void build_row_ptr_edges(const int* __restrict__ rows, int E, int N) {
    int e = blockIdx.x * blockDim.x + threadIdx.x;
    if (e >= E) return;
    int r     = __ldg(&rows[e]);
    int rprev = (e == 0) ? -1 : __ldg(&rows[e - 1]);
    for (int rr = rprev + 1; rr <= r; rr++) g_row_ptr[rr] = e;
    if (e == E - 1) {
        for (int rr = r + 1; rr <= N; rr++) g_row_ptr[rr] = E;
    }
}

__global__ void __launch_bounds__(TPR * RPB)
spmm_csr_vec_kernel(const float4* __restrict__ x4,
                    const int*    __restrict__ cols,
                    const float*  __restrict__ vals,
                    float4*       __restrict__ out4,
                    int N) {
    const int row = blockIdx.x * RPB + threadIdx.y;
    if (row >= N) return;
    const int fl = threadIdx.x;              // 0..11: float4 slot in the row

    int e   = g_row_ptr[row];
    const int end = g_row_ptr[row + 1];

    float4 acc = make_float4(0.f, 0.f, 0.f, 0.f);

    // Unroll by 2 for memory-level parallelism (unroll-4 measured slower:
    // warp straddles 2.67 rows, deeper unroll amplifies divergence).
    for (; e + 1 < end; e += 2) {
        const int   c0 = __ldg(&cols[e]);
        const int   c1 = __ldg(&cols[e + 1]);
        const float v0 = __ldg(&vals[e]);
        const float v1 = __ldg(&vals[e + 1]);
        const float4 b0 = __ldg(&x4[(size_t)c0 * D_VEC + fl]);
        const float4 b1 = __ldg(&x4[(size_t)c1 * D_VEC + fl]);
        acc.x = fmaf(v0, b0.x, acc.x);
        acc.y = fmaf(v0, b0.y, acc.y);
        acc.z = fmaf(v0, b0.z, acc.z);
        acc.w = fmaf(v0, b0.w, acc.w);
        acc.x = fmaf(v1, b1.x, acc.x);
        acc.y = fmaf(v1, b1.y, acc.y);
        acc.z = fmaf(v1, b1.z, acc.z);
        acc.w = fmaf(v1, b1.w, acc.w);
    }
    if (e < end) {
        const int   c = __ldg(&cols[e]);
        const float v = __ldg(&vals[e]);
        const float4 b = __ldg(&x4[(size_t)c * D_VEC + fl]);
        acc.x = fmaf(v, b.x, acc.x);
        acc.y = fmaf(v, b.y, acc.y);
        acc.z = fmaf(v, b.z, acc.z);
        acc.w = fmaf(v, b.w, acc.w);
    }

    out4[(size_t)row * D_VEC + fl] = acc;
}

extern "C" void kernel_launch(void* const* d_in, const int* in_sizes, int n_in,
                              void* d_out, int out_size) {
    // metadata order: t, x, rows, cols, vals
    const float* x    = (const float*)d_in[1];
    const int*   rows = (const int*)d_in[2];
    const int*   cols = (const int*)d_in[3];
    const float* vals = (const float*)d_in[4];
    float*       out  = (float*)d_out;

    const int E = in_sizes[2];
    const int N = out_size / D_FEAT;

    {
        int threads = 256;
        int blocks  = (E + threads - 1) / threads;
        build_row_ptr_edges<<<blocks, threads>>>(rows, E, N);
    }
    {
        dim3 block(TPR, RPB);
        int  grid = (N + RPB - 1) / RPB;
        spmm_csr_vec_kernel<<<grid, block>>>((const float4*)x, cols, vals,
                                             (float4*)out, N);
    }
}

// round 9
// speedup vs baseline: 1.1731x; 1.0388x over previous
#include <cuda_runtime.h>
#include <cuda_bf16.h>
#include <cuda_fp16.h>

// COO SpMM, rows sorted: out[r] = sum_{(r,c,v)} v * x[c].  N=100000, E=1.6M, D=48.
// R9: measured state = L2-bandwidth wall (~357MB L2 traffic @ ~10TB/s = 35us;
// all structural variants converge there). Lever: halve gathered bytes.
// Convert x to fp16 once per launch (fp32 accumulate keeps rel_err ~2e-4,
// under the 1e-3 gate), gather 96B/row via LDG.64 instead of 192B LDG.128.
// Same row-parallel CSR structure as the best kernel (R3/R8), unroll-2.

#define D_FEAT    48
#define D_VEC     12           // 12 x uint2(4 halves) per row
#define TPR       12
#define RPB       16
#define MAX_NODES 100000

__device__ int    g_row_ptr[MAX_NODES + 1];
__device__ __half g_xh[(size_t)MAX_NODES * D_FEAT];   // 9.6 MB fp16 copy of x

// Edge-parallel CSR row-pointer build: thread e fills row starts in
// (rows[e-1], rows[e]].
__global__ void build_row_ptr_edges(const int* __restrict__ rows, int E, int N) {
    int e = blockIdx.x * blockDim.x + threadIdx.x;
    if (e >= E) return;
    int r     = __ldg(&rows[e]);
    int rprev = (e == 0) ? -1 : __ldg(&rows[e - 1]);
    for (int rr = rprev + 1; rr <= r; rr++) g_row_ptr[rr] = e;
    if (e == E - 1) {
        for (int rr = r + 1; rr <= N; rr++) g_row_ptr[rr] = E;
    }
}

// Convert x (fp32) -> g_xh (fp16). 8 floats per thread: 2x LDG.128, 1x STG.128.
__global__ void convert_x_half(const float4* __restrict__ x4, int n_vec8) {
    int i = blockIdx.x * blockDim.x + threadIdx.x;   // one 8-float chunk
    if (i >= n_vec8) return;
    float4 a = __ldg(&x4[2 * i]);
    float4 b = __ldg(&x4[2 * i + 1]);
    half2 h0 = __floats2half2_rn(a.x, a.y);
    half2 h1 = __floats2half2_rn(a.z, a.w);
    half2 h2 = __floats2half2_rn(b.x, b.y);
    half2 h3 = __floats2half2_rn(b.z, b.w);
    uint4 out;
    out.x = *reinterpret_cast<unsigned*>(&h0);
    out.y = *reinterpret_cast<unsigned*>(&h1);
    out.z = *reinterpret_cast<unsigned*>(&h2);
    out.w = *reinterpret_cast<unsigned*>(&h3);
    reinterpret_cast<uint4*>(g_xh)[i] = out;
}

__device__ __forceinline__ void fma_edge(float4& acc, float v, uint2 u) {
    half2 h0 = *reinterpret_cast<half2*>(&u.x);
    half2 h1 = *reinterpret_cast<half2*>(&u.y);
    float2 f0 = __half22float2(h0);
    float2 f1 = __half22float2(h1);
    acc.x = fmaf(v, f0.x, acc.x);
    acc.y = fmaf(v, f0.y, acc.y);
    acc.z = fmaf(v, f1.x, acc.z);
    acc.w = fmaf(v, f1.y, acc.w);
}

__global__ void __launch_bounds__(TPR * RPB)
spmm_csr_h_kernel(const int*   __restrict__ cols,
                  const float* __restrict__ vals,
                  float4*      __restrict__ out4,
                  int N) {
    const int row = blockIdx.x * RPB + threadIdx.y;
    if (row >= N) return;
    const int fl = threadIdx.x;              // 0..11: 4-half slot in the row

    int e   = g_row_ptr[row];
    const int end = g_row_ptr[row + 1];

    const uint2* __restrict__ xh2 = reinterpret_cast<const uint2*>(g_xh);

    float4 acc = make_float4(0.f, 0.f, 0.f, 0.f);

    for (; e + 1 < end; e += 2) {
        const int   c0 = __ldg(&cols[e]);
        const int   c1 = __ldg(&cols[e + 1]);
        const float v0 = __ldg(&vals[e]);
        const float v1 = __ldg(&vals[e + 1]);
        const uint2 b0 = __ldg(&xh2[(size_t)c0 * D_VEC + fl]);
        const uint2 b1 = __ldg(&xh2[(size_t)c1 * D_VEC + fl]);
        fma_edge(acc, v0, b0);
        fma_edge(acc, v1, b1);
    }
    if (e < end) {
        const int   c = __ldg(&cols[e]);
        const float v = __ldg(&vals[e]);
        const uint2 b = __ldg(&xh2[(size_t)c * D_VEC + fl]);
        fma_edge(acc, v, b);
    }

    out4[(size_t)row * D_VEC + fl] = acc;
}

extern "C" void kernel_launch(void* const* d_in, const int* in_sizes, int n_in,
                              void* d_out, int out_size) {
    // metadata order: t, x, rows, cols, vals
    const float* x    = (const float*)d_in[1];
    const int*   rows = (const int*)d_in[2];
    const int*   cols = (const int*)d_in[3];
    const float* vals = (const float*)d_in[4];
    float*       out  = (float*)d_out;

    const int E = in_sizes[2];
    const int N = out_size / D_FEAT;

    {
        int threads = 256;
        int blocks  = (E + threads - 1) / threads;
        build_row_ptr_edges<<<blocks, threads>>>(rows, E, N);
    }
    {
        int n_vec8  = (N * D_FEAT) / 8;          // 600000 8-float chunks
        int threads = 256;
        int blocks  = (n_vec8 + threads - 1) / threads;
        convert_x_half<<<blocks, threads>>>((const float4*)x, n_vec8);
    }
    {
        dim3 block(TPR, RPB);
        int  grid = (N + RPB - 1) / RPB;
        spmm_csr_h_kernel<<<grid, block>>>(cols, vals, (float4*)out, N);
    }
}